// round 1
// baseline (speedup 1.0000x reference)
#include <cuda_runtime.h>
#include <math.h>

// ---------------- problem constants ----------------
#define BQ     2
#define TT     8
#define HDIM   64
#define WDIM   64
#define CC     192
#define HEADS  6
#define DH     32
#define NTOK   256     // tokens per window (4*8*8)
#define NWIN   128     // windows per batch (2*8*8)
#define BWIN   256     // total windows
#define MROWS  65536   // B*T*H*W  (== BWIN*NTOK)
#define HID    768
#define CPB_M  1575    // 7*15*15
#define CPB_H  512

// ---------------- scratch (device globals; no runtime alloc allowed) ----------------
__device__ float g_xw [MROWS * CC];        // windowed input, later attention output
__device__ float g_qkv[MROWS * 3 * CC];    // qkv
__device__ float g_pr [MROWS * CC];        // proj out, later fc2 out
__device__ float g_x1 [MROWS * CC];        // attention residual result (global layout)
__device__ float g_h1 [MROWS * HID];       // MLP hidden
__device__ float g_tbl[CPB_M * HEADS];     // 16*sigmoid(cpb) per rel-coord, per head
__device__ float g_scale[HEADS];           // exp(min(logit_scale, log 100))

// ---------------- CPB table: tbl = 16*sigmoid(relu(rel@w1^T+b1)@w2^T) ----------------
__global__ void cpb_kernel(const float* __restrict__ w1, const float* __restrict__ b1,
                           const float* __restrict__ w2, const float* __restrict__ ls) {
    int m = blockIdx.x;
    int tid = threadIdx.x;
    if (m == 0 && tid < HEADS)
        g_scale[tid] = expf(fminf(ls[tid], logf(100.0f)));

    int i = m / 225, rem = m % 225, j = rem / 15, k = rem % 15;
    float v0 = (float)(i - 3) * (8.0f / 3.0f);
    float v1 = (float)(j - 7) * (8.0f / 7.0f);
    float v2 = (float)(k - 7) * (8.0f / 7.0f);
    const float inv_l8 = 1.0f / log2f(8.0f);
    float c0 = copysignf(log2f(fabsf(v0) + 1.0f) * inv_l8, v0);
    float c1 = copysignf(log2f(fabsf(v1) + 1.0f) * inv_l8, v1);
    float c2 = copysignf(log2f(fabsf(v2) + 1.0f) * inv_l8, v2);

    float h = c0 * w1[tid * 3 + 0] + c1 * w1[tid * 3 + 1] + c2 * w1[tid * 3 + 2] + b1[tid];
    h = fmaxf(h, 0.0f);

    __shared__ float red[CPB_H];
    for (int hh = 0; hh < HEADS; hh++) {
        red[tid] = h * w2[hh * CPB_H + tid];
        __syncthreads();
        for (int s = CPB_H / 2; s > 0; s >>= 1) {
            if (tid < s) red[tid] += red[tid + s];
            __syncthreads();
        }
        if (tid == 0) {
            float t = red[0];
            g_tbl[m * HEADS + hh] = 16.0f / (1.0f + expf(-t));  // fold 16*sigmoid here
        }
        __syncthreads();
    }
}

// ---------------- shift + window partition (gather) ----------------
__global__ void gather_kernel(const float* __restrict__ x) {
    int idx = blockIdx.x * 256 + threadIdx.x;           // over MROWS*CC
    int r = idx / CC, c = idx % CC;
    int b_ = r >> 8, n = r & 255;
    int bb = b_ >> 7, w_ = b_ & 127;
    int wt = w_ >> 6, wh = (w_ >> 3) & 7, ww = w_ & 7;
    int it = n >> 6, ih = (n >> 3) & 7, iw = n & 7;
    int t = (wt * 4 + it + 2) & 7;       // roll -SHIFT => read from +SHIFT
    int h = (wh * 8 + ih + 4) & 63;
    int w = (ww * 8 + iw + 4) & 63;
    int src = ((bb * TT + t) * HDIM + h) * WDIM + w;
    g_xw[idx] = x[(long)src * CC + c];
}

// ---------------- generic tiled fp32 GEMM: C[M,N] = A[M,K] @ W[N,K]^T + bias ----------------
template <int ACT>
__device__ __forceinline__ void gemm_body(const float* __restrict__ A, const float* __restrict__ Wt,
                                          const float* __restrict__ bias, float* __restrict__ Cm,
                                          int M, int Nn, int K) {
    __shared__ float As[16][68];
    __shared__ float Bs[16][68];
    int tid = threadIdx.x;
    int tx = tid & 15, ty = tid >> 4;
    int n0 = blockIdx.x * 64, m0 = blockIdx.y * 64;
    float acc[4][4] = {};
    for (int k0 = 0; k0 < K; k0 += 16) {
        #pragma unroll
        for (int i = 0; i < 4; i++) {
            int e = tid + i * 256;
            int kk = e & 15, r = e >> 4;
            As[kk][r] = A[(long)(m0 + r) * K + k0 + kk];
            Bs[kk][r] = Wt[(long)(n0 + r) * K + k0 + kk];
        }
        __syncthreads();
        #pragma unroll
        for (int kk = 0; kk < 16; kk++) {
            float4 a4 = *(const float4*)&As[kk][ty * 4];
            float4 b4 = *(const float4*)&Bs[kk][tx * 4];
            float a[4] = {a4.x, a4.y, a4.z, a4.w};
            float b[4] = {b4.x, b4.y, b4.z, b4.w};
            #pragma unroll
            for (int i = 0; i < 4; i++)
                #pragma unroll
                for (int j = 0; j < 4; j++)
                    acc[i][j] += a[i] * b[j];
        }
        __syncthreads();
    }
    #pragma unroll
    for (int i = 0; i < 4; i++) {
        int mr = m0 + ty * 4 + i;
        #pragma unroll
        for (int j = 0; j < 4; j++) {
            int nc = n0 + tx * 4 + j;
            float c = acc[i][j] + bias[nc];
            if (ACT == 1) c = 0.5f * c * (1.0f + erff(c * 0.70710678118654752f));
            Cm[(long)mr * Nn + nc] = c;
        }
    }
}

__global__ void gemm_qkv_k (const float* Wt, const float* b) { gemm_body<0>(g_xw, Wt, b, g_qkv, MROWS, 3 * CC, CC); }
__global__ void gemm_proj_k(const float* Wt, const float* b) { gemm_body<0>(g_xw, Wt, b, g_pr,  MROWS, CC,     CC); }
__global__ void gemm_fc1_k (const float* Wt, const float* b) { gemm_body<1>(g_x1, Wt, b, g_h1,  MROWS, HID,    CC); }
__global__ void gemm_fc2_k (const float* Wt, const float* b) { gemm_body<0>(g_h1, Wt, b, g_pr,  MROWS, CC,    HID); }

// ---------------- pre-normalize q,k rows (cosine attention); fold scale into q ----------------
__global__ void prenorm_kernel() {
    int gw = (blockIdx.x * blockDim.x + threadIdx.x) >> 5;   // global warp id
    int lane = threadIdx.x & 31;
    int which = gw & 1;        // 0 = q, 1 = k
    int tmp = gw >> 1;
    int hh = tmp % HEADS;
    int row = tmp / HEADS;     // < MROWS
    float* p = &g_qkv[(long)row * (3 * CC) + which * CC + hh * DH + lane];
    float v = *p;
    float ss = v * v;
    #pragma unroll
    for (int o = 16; o; o >>= 1) ss += __shfl_xor_sync(0xffffffffu, ss, o);
    float rn = 1.0f / fmaxf(sqrtf(ss), 1e-12f);
    if (which == 0) rn *= g_scale[hh];
    *p = v * rn;
}

// ---------------- windowed attention (one block per (window, head)) ----------------
__global__ void attn_kernel() {
    int b_ = blockIdx.x / HEADS;
    int hh = blockIdx.x % HEADS;
    int n = threadIdx.x;  // query token, 0..255

    __shared__ float k_sh[128 * 32];
    __shared__ float v_sh[128 * 32];
    __shared__ float tbl_sh[CPB_M];
    __shared__ int   reg_sh[NTOK];

    for (int i = n; i < CPB_M; i += 256) tbl_sh[i] = g_tbl[i * HEADS + hh];
    {
        int w_ = b_ & 127;
        int wt = w_ >> 6, wh = (w_ >> 3) & 7, ww = w_ & 7;
        int it = n >> 6, ih = (n >> 3) & 7, iw = n & 7;
        int ts = wt * 4 + it, hs = wh * 8 + ih, ws = ww * 8 + iw;
        int dt = (ts < 4) ? 0 : (ts < 6 ? 1 : 2);
        int dh = (hs < 56) ? 0 : (hs < 60 ? 1 : 2);
        int dw = (ws < 56) ? 0 : (ws < 60 ? 1 : 2);
        reg_sh[n] = dt * 9 + dh * 3 + dw;
    }
    __syncthreads();

    const float* qrow = &g_qkv[((long)b_ * NTOK + n) * (3 * CC) + hh * DH];
    float q[32];
    #pragma unroll
    for (int dd = 0; dd < 32; dd++) q[dd] = qrow[dd];
    int it = n >> 6, ih = (n >> 3) & 7, iw = n & 7;
    int myreg = reg_sh[n];

    // PASS 1: row max
    float maxv = -1e30f;
    for (int t = 0; t < 2; t++) {
        __syncthreads();
        #pragma unroll
        for (int i = 0; i < 16; i++) {
            int e = i * 256 + n;
            int ml = e >> 5, dd = e & 31;
            k_sh[e] = g_qkv[((long)b_ * NTOK + t * 128 + ml) * (3 * CC) + CC + hh * DH + dd];
        }
        __syncthreads();
        for (int ml = 0; ml < 128; ml++) {
            int m = t * 128 + ml;
            float dot = 0.0f;
            #pragma unroll
            for (int dd = 0; dd < 32; dd++) dot += q[dd] * k_sh[ml * 32 + dd];
            int jt = m >> 6, jh = (m >> 3) & 7, jw = m & 7;
            int idx = ((it - jt + 3) * 15 + (ih - jh + 7)) * 15 + (iw - jw + 7);
            float logit = dot + tbl_sh[idx] + ((reg_sh[m] == myreg) ? 0.0f : -100.0f);
            maxv = fmaxf(maxv, logit);
        }
    }

    // PASS 2: exp-sum + PV
    float denom = 0.0f;
    float out[32];
    #pragma unroll
    for (int dd = 0; dd < 32; dd++) out[dd] = 0.0f;
    for (int t = 0; t < 2; t++) {
        __syncthreads();
        #pragma unroll
        for (int i = 0; i < 16; i++) {
            int e = i * 256 + n;
            int ml = e >> 5, dd = e & 31;
            long base = ((long)b_ * NTOK + t * 128 + ml) * (3 * CC);
            k_sh[e] = g_qkv[base + CC + hh * DH + dd];
            v_sh[e] = g_qkv[base + 2 * CC + hh * DH + dd];
        }
        __syncthreads();
        for (int ml = 0; ml < 128; ml++) {
            int m = t * 128 + ml;
            float dot = 0.0f;
            #pragma unroll
            for (int dd = 0; dd < 32; dd++) dot += q[dd] * k_sh[ml * 32 + dd];
            int jt = m >> 6, jh = (m >> 3) & 7, jw = m & 7;
            int idx = ((it - jt + 3) * 15 + (ih - jh + 7)) * 15 + (iw - jw + 7);
            float logit = dot + tbl_sh[idx] + ((reg_sh[m] == myreg) ? 0.0f : -100.0f);
            float e2 = expf(logit - maxv);
            denom += e2;
            #pragma unroll
            for (int dd = 0; dd < 32; dd++) out[dd] += e2 * v_sh[ml * 32 + dd];
        }
    }
    float rd = 1.0f / denom;
    float* orow = &g_xw[((long)b_ * NTOK + n) * CC + hh * DH];
    #pragma unroll
    for (int dd = 0; dd < 32; dd++) orow[dd] = out[dd] * rd;
}

// ---------------- LN(proj) + residual, scatter back to global layout ----------------
__global__ void attn_post_kernel(const float* __restrict__ x,
                                 const float* __restrict__ g, const float* __restrict__ b) {
    int r = blockIdx.x;       // window-token row
    int c = threadIdx.x;      // 0..255
    bool act = c < CC;
    float v = act ? g_pr[(long)r * CC + c] : 0.0f;
    __shared__ float s1[256], s2[256];
    s1[c] = v; s2[c] = v * v;
    __syncthreads();
    for (int s = 128; s > 0; s >>= 1) {
        if (c < s) { s1[c] += s1[c + s]; s2[c] += s2[c + s]; }
        __syncthreads();
    }
    float mean = s1[0] * (1.0f / CC);
    float var = s2[0] * (1.0f / CC) - mean * mean;
    if (act) {
        float ln = (v - mean) * rsqrtf(var + 1e-5f) * g[c] + b[c];
        int b_ = r >> 8, n = r & 255;
        int bb = b_ >> 7, w_ = b_ & 127;
        int wt = w_ >> 6, wh = (w_ >> 3) & 7, ww = w_ & 7;
        int it = n >> 6, ih = (n >> 3) & 7, iw = n & 7;
        int t = (wt * 4 + it + 2) & 7;
        int h = (wh * 8 + ih + 4) & 63;
        int w = (ww * 8 + iw + 4) & 63;
        long dst = ((long)((bb * TT + t) * HDIM + h) * WDIM + w) * CC + c;
        g_x1[dst] = x[dst] + ln;
    }
}

// ---------------- final LN(fc2) + residual -> output ----------------
__global__ void final_kernel(float* __restrict__ out,
                             const float* __restrict__ g, const float* __restrict__ b) {
    int r = blockIdx.x;
    int c = threadIdx.x;
    bool act = c < CC;
    float v = act ? g_pr[(long)r * CC + c] : 0.0f;
    __shared__ float s1[256], s2[256];
    s1[c] = v; s2[c] = v * v;
    __syncthreads();
    for (int s = 128; s > 0; s >>= 1) {
        if (c < s) { s1[c] += s1[c + s]; s2[c] += s2[c + s]; }
        __syncthreads();
    }
    float mean = s1[0] * (1.0f / CC);
    float var = s2[0] * (1.0f / CC) - mean * mean;
    if (act) {
        float ln = (v - mean) * rsqrtf(var + 1e-5f) * g[c] + b[c];
        out[(long)r * CC + c] = g_x1[(long)r * CC + c] + ln;
    }
}

// ---------------- launch ----------------
extern "C" void kernel_launch(void* const* d_in, const int* in_sizes, int n_in,
                              void* d_out, int out_size) {
    const float* x      = (const float*)d_in[0];
    const float* qkv_w  = (const float*)d_in[1];
    const float* qkv_b  = (const float*)d_in[2];
    const float* proj_w = (const float*)d_in[3];
    const float* proj_b = (const float*)d_in[4];
    const float* cpb_w1 = (const float*)d_in[5];
    const float* cpb_b1 = (const float*)d_in[6];
    const float* cpb_w2 = (const float*)d_in[7];
    const float* ls     = (const float*)d_in[8];
    const float* n1g    = (const float*)d_in[9];
    const float* n1b    = (const float*)d_in[10];
    const float* n2g    = (const float*)d_in[11];
    const float* n2b    = (const float*)d_in[12];
    const float* fc1_w  = (const float*)d_in[13];
    const float* fc1_b  = (const float*)d_in[14];
    const float* fc2_w  = (const float*)d_in[15];
    const float* fc2_b  = (const float*)d_in[16];
    float* out = (float*)d_out;

    cpb_kernel<<<CPB_M, CPB_H>>>(cpb_w1, cpb_b1, cpb_w2, ls);
    gather_kernel<<<(MROWS * CC) / 256, 256>>>(x);
    gemm_qkv_k<<<dim3((3 * CC) / 64, MROWS / 64), 256>>>(qkv_w, qkv_b);
    prenorm_kernel<<<(MROWS * HEADS * 2) / 8, 256>>>();
    attn_kernel<<<BWIN * HEADS, 256>>>();
    gemm_proj_k<<<dim3(CC / 64, MROWS / 64), 256>>>(proj_w, proj_b);
    attn_post_kernel<<<MROWS, 256>>>(x, n1g, n1b);
    gemm_fc1_k<<<dim3(HID / 64, MROWS / 64), 256>>>(fc1_w, fc1_b);
    gemm_fc2_k<<<dim3(CC / 64, MROWS / 64), 256>>>(fc2_w, fc2_b);
    final_kernel<<<MROWS, 256>>>(out, n2g, n2b);
}

// round 3
// speedup vs baseline: 1.5989x; 1.5989x over previous
#include <cuda_runtime.h>
#include <stdint.h>
#include <math.h>

// ---------------- problem constants ----------------
#define BQ     2
#define TT     8
#define HDIM   64
#define WDIM   64
#define CC     192
#define HEADS  6
#define DH     32
#define NTOK   256     // tokens per window (4*8*8)
#define NWIN   128     // windows per batch (2*8*8)
#define BWIN   256     // total windows
#define MROWS  65536   // B*T*H*W  (== BWIN*NTOK)
#define HID    768
#define CPB_M  1575    // 7*15*15
#define CPB_H  512

// ---------------- scratch (device globals; no runtime alloc allowed) ----------------
__device__ float g_xw [MROWS * CC];        // windowed input, later attention output
__device__ float g_qkv[MROWS * 3 * CC];    // qkv
__device__ float g_pr [MROWS * CC];        // proj out, later fc2 out
__device__ float g_x1 [MROWS * CC];        // attention residual result (global layout)
__device__ float g_h1 [MROWS * HID];       // MLP hidden
__device__ float g_tbl[CPB_M * HEADS];     // 16*sigmoid(cpb) per rel-coord, per head
__device__ float g_scale[HEADS];           // exp(min(logit_scale, log 100))

// ---------------- CPB table ----------------
__global__ void cpb_kernel(const float* __restrict__ w1, const float* __restrict__ b1,
                           const float* __restrict__ w2, const float* __restrict__ ls) {
    int m = blockIdx.x;
    int tid = threadIdx.x;
    if (m == 0 && tid < HEADS)
        g_scale[tid] = expf(fminf(ls[tid], logf(100.0f)));

    int i = m / 225, rem = m % 225, j = rem / 15, k = rem % 15;
    float v0 = (float)(i - 3) * (8.0f / 3.0f);
    float v1 = (float)(j - 7) * (8.0f / 7.0f);
    float v2 = (float)(k - 7) * (8.0f / 7.0f);
    const float inv_l8 = 1.0f / log2f(8.0f);
    float c0 = copysignf(log2f(fabsf(v0) + 1.0f) * inv_l8, v0);
    float c1 = copysignf(log2f(fabsf(v1) + 1.0f) * inv_l8, v1);
    float c2 = copysignf(log2f(fabsf(v2) + 1.0f) * inv_l8, v2);

    float h = c0 * w1[tid * 3 + 0] + c1 * w1[tid * 3 + 1] + c2 * w1[tid * 3 + 2] + b1[tid];
    h = fmaxf(h, 0.0f);

    __shared__ float red[CPB_H];
    for (int hh = 0; hh < HEADS; hh++) {
        red[tid] = h * w2[hh * CPB_H + tid];
        __syncthreads();
        for (int s = CPB_H / 2; s > 0; s >>= 1) {
            if (tid < s) red[tid] += red[tid + s];
            __syncthreads();
        }
        if (tid == 0) {
            float t = red[0];
            g_tbl[m * HEADS + hh] = 16.0f / (1.0f + expf(-t));
        }
        __syncthreads();
    }
}

// ---------------- shift + window partition (gather) ----------------
__global__ void gather_kernel(const float* __restrict__ x) {
    int idx = blockIdx.x * 256 + threadIdx.x;           // over MROWS*CC
    int r = idx / CC, c = idx % CC;
    int b_ = r >> 8, n = r & 255;
    int bb = b_ >> 7, w_ = b_ & 127;
    int wt = w_ >> 6, wh = (w_ >> 3) & 7, ww = w_ & 7;
    int it = n >> 6, ih = (n >> 3) & 7, iw = n & 7;
    int t = (wt * 4 + it + 2) & 7;
    int h = (wh * 8 + ih + 4) & 63;
    int w = (ww * 8 + iw + 4) & 63;
    int src = ((bb * TT + t) * HDIM + h) * WDIM + w;
    g_xw[idx] = x[(long)src * CC + c];
}

// ---------------- tf32 tensor-core GEMM: C[M,N] = A[M,K] @ W[N,K]^T + bias ----------------
// 128x64 CTA tile, BK=16, 256 threads (8 warps: 4 along M x 2 along N), warp tile 32x32.
__device__ __forceinline__ uint32_t f2tf32(float f) {
    uint32_t u;
    asm("cvt.rna.tf32.f32 %0, %1;" : "=r"(u) : "f"(f));
    return u;
}

template <int ACT>
__device__ __forceinline__ void gemm_tc_body(const float* __restrict__ A, const float* __restrict__ Wt,
                                             const float* __restrict__ bias, float* __restrict__ Cm,
                                             int M, int Nn, int K) {
    __shared__ uint32_t As[128][20];   // [row][k] pad->20 (conflict-free frag loads)
    __shared__ uint32_t Bs[64][20];    // [col][k]

    int tid = threadIdx.x;
    int lane = tid & 31;
    int warp = tid >> 5;
    int wm = warp >> 1;            // 0..3
    int wn = warp & 1;             // 0..1
    int m0 = blockIdx.y * 128;
    int n0 = blockIdx.x * 64;

    int grp = lane >> 2;           // 0..7
    int kc  = lane & 3;            // 0..3

    float acc[2][4][4];
    #pragma unroll
    for (int i = 0; i < 2; i++)
        #pragma unroll
        for (int j = 0; j < 4; j++)
            #pragma unroll
            for (int q = 0; q < 4; q++) acc[i][j][q] = 0.0f;

    for (int k0 = 0; k0 < K; k0 += 16) {
        // global -> smem (with tf32 convert)
        #pragma unroll
        for (int i = 0; i < 2; i++) {
            int e = i * 256 + tid;           // 0..511
            int r = e >> 2;                  // 0..127
            int kq = (e & 3) * 4;
            float4 v = *(const float4*)&A[(long)(m0 + r) * K + k0 + kq];
            As[r][kq + 0] = f2tf32(v.x);
            As[r][kq + 1] = f2tf32(v.y);
            As[r][kq + 2] = f2tf32(v.z);
            As[r][kq + 3] = f2tf32(v.w);
        }
        {
            int r = tid >> 2;                // 0..63
            int kq = (tid & 3) * 4;
            float4 v = *(const float4*)&Wt[(long)(n0 + r) * K + k0 + kq];
            Bs[r][kq + 0] = f2tf32(v.x);
            Bs[r][kq + 1] = f2tf32(v.y);
            Bs[r][kq + 2] = f2tf32(v.z);
            Bs[r][kq + 3] = f2tf32(v.w);
        }
        __syncthreads();

        #pragma unroll
        for (int ks = 0; ks < 2; ks++) {
            int kb = ks * 8 + kc;
            uint32_t af[2][4];
            #pragma unroll
            for (int mt = 0; mt < 2; mt++) {
                int r = wm * 32 + mt * 16 + grp;
                af[mt][0] = As[r][kb];
                af[mt][1] = As[r + 8][kb];
                af[mt][2] = As[r][kb + 4];
                af[mt][3] = As[r + 8][kb + 4];
            }
            uint32_t bf[4][2];
            #pragma unroll
            for (int nt = 0; nt < 4; nt++) {
                int c = wn * 32 + nt * 8 + grp;
                bf[nt][0] = Bs[c][kb];
                bf[nt][1] = Bs[c][kb + 4];
            }
            #pragma unroll
            for (int mt = 0; mt < 2; mt++)
                #pragma unroll
                for (int nt = 0; nt < 4; nt++) {
                    asm volatile(
                        "mma.sync.aligned.m16n8k8.row.col.f32.tf32.tf32.f32 "
                        "{%0,%1,%2,%3}, {%4,%5,%6,%7}, {%8,%9}, {%0,%1,%2,%3};\n"
                        : "+f"(acc[mt][nt][0]), "+f"(acc[mt][nt][1]),
                          "+f"(acc[mt][nt][2]), "+f"(acc[mt][nt][3])
                        : "r"(af[mt][0]), "r"(af[mt][1]), "r"(af[mt][2]), "r"(af[mt][3]),
                          "r"(bf[nt][0]), "r"(bf[nt][1]));
                }
        }
        __syncthreads();
    }

    // epilogue
    #pragma unroll
    for (int mt = 0; mt < 2; mt++) {
        int row = m0 + wm * 32 + mt * 16 + grp;
        #pragma unroll
        for (int nt = 0; nt < 4; nt++) {
            int col = n0 + wn * 32 + nt * 8 + kc * 2;
            float b0 = bias[col], b1 = bias[col + 1];
            float c0 = acc[mt][nt][0] + b0;
            float c1 = acc[mt][nt][1] + b1;
            float c2 = acc[mt][nt][2] + b0;
            float c3 = acc[mt][nt][3] + b1;
            if (ACT == 1) {
                c0 = 0.5f * c0 * (1.0f + erff(c0 * 0.70710678118654752f));
                c1 = 0.5f * c1 * (1.0f + erff(c1 * 0.70710678118654752f));
                c2 = 0.5f * c2 * (1.0f + erff(c2 * 0.70710678118654752f));
                c3 = 0.5f * c3 * (1.0f + erff(c3 * 0.70710678118654752f));
            }
            *(float2*)&Cm[(long)row * Nn + col] = make_float2(c0, c1);
            *(float2*)&Cm[(long)(row + 8) * Nn + col] = make_float2(c2, c3);
        }
    }
}

__global__ void __launch_bounds__(256) gemm_qkv_k (const float* Wt, const float* b) { gemm_tc_body<0>(g_xw, Wt, b, g_qkv, MROWS, 3 * CC, CC); }
__global__ void __launch_bounds__(256) gemm_proj_k(const float* Wt, const float* b) { gemm_tc_body<0>(g_xw, Wt, b, g_pr,  MROWS, CC,     CC); }
__global__ void __launch_bounds__(256) gemm_fc1_k (const float* Wt, const float* b) { gemm_tc_body<1>(g_x1, Wt, b, g_h1,  MROWS, HID,    CC); }
__global__ void __launch_bounds__(256) gemm_fc2_k (const float* Wt, const float* b) { gemm_tc_body<0>(g_h1, Wt, b, g_pr,  MROWS, CC,    HID); }

// ---------------- pre-normalize q,k rows; fold scale into q ----------------
__global__ void prenorm_kernel() {
    int gw = (blockIdx.x * blockDim.x + threadIdx.x) >> 5;
    int lane = threadIdx.x & 31;
    int which = gw & 1;
    int tmp = gw >> 1;
    int hh = tmp % HEADS;
    int row = tmp / HEADS;
    float* p = &g_qkv[(long)row * (3 * CC) + which * CC + hh * DH + lane];
    float v = *p;
    float ss = v * v;
    #pragma unroll
    for (int o = 16; o; o >>= 1) ss += __shfl_xor_sync(0xffffffffu, ss, o);
    float rn = 1.0f / fmaxf(sqrtf(ss), 1e-12f);
    if (which == 0) rn *= g_scale[hh];
    *p = v * rn;
}

// ---------------- windowed attention (one block per (window, head)) ----------------
__global__ void attn_kernel() {
    int b_ = blockIdx.x / HEADS;
    int hh = blockIdx.x % HEADS;
    int n = threadIdx.x;

    __shared__ float k_sh[128 * 32];
    __shared__ float v_sh[128 * 32];
    __shared__ float tbl_sh[CPB_M];
    __shared__ int   reg_sh[NTOK];

    for (int i = n; i < CPB_M; i += 256) tbl_sh[i] = g_tbl[i * HEADS + hh];
    {
        int w_ = b_ & 127;
        int wt = w_ >> 6, wh = (w_ >> 3) & 7, ww = w_ & 7;
        int it = n >> 6, ih = (n >> 3) & 7, iw = n & 7;
        int ts = wt * 4 + it, hs = wh * 8 + ih, ws = ww * 8 + iw;
        int dt = (ts < 4) ? 0 : (ts < 6 ? 1 : 2);
        int dh = (hs < 56) ? 0 : (hs < 60 ? 1 : 2);
        int dw = (ws < 56) ? 0 : (ws < 60 ? 1 : 2);
        reg_sh[n] = dt * 9 + dh * 3 + dw;
    }
    __syncthreads();

    const float* qrow = &g_qkv[((long)b_ * NTOK + n) * (3 * CC) + hh * DH];
    float q[32];
    #pragma unroll
    for (int dd = 0; dd < 32; dd++) q[dd] = qrow[dd];
    int it = n >> 6, ih = (n >> 3) & 7, iw = n & 7;
    int myreg = reg_sh[n];

    // PASS 1: row max
    float maxv = -1e30f;
    for (int t = 0; t < 2; t++) {
        __syncthreads();
        #pragma unroll
        for (int i = 0; i < 16; i++) {
            int e = i * 256 + n;
            int ml = e >> 5, dd = e & 31;
            k_sh[e] = g_qkv[((long)b_ * NTOK + t * 128 + ml) * (3 * CC) + CC + hh * DH + dd];
        }
        __syncthreads();
        for (int ml = 0; ml < 128; ml++) {
            int m = t * 128 + ml;
            float dot = 0.0f;
            #pragma unroll
            for (int dd = 0; dd < 32; dd++) dot += q[dd] * k_sh[ml * 32 + dd];
            int jt = m >> 6, jh = (m >> 3) & 7, jw = m & 7;
            int idx = ((it - jt + 3) * 15 + (ih - jh + 7)) * 15 + (iw - jw + 7);
            float logit = dot + tbl_sh[idx] + ((reg_sh[m] == myreg) ? 0.0f : -100.0f);
            maxv = fmaxf(maxv, logit);
        }
    }

    // PASS 2: exp-sum + PV
    float denom = 0.0f;
    float out[32];
    #pragma unroll
    for (int dd = 0; dd < 32; dd++) out[dd] = 0.0f;
    for (int t = 0; t < 2; t++) {
        __syncthreads();
        #pragma unroll
        for (int i = 0; i < 16; i++) {
            int e = i * 256 + n;
            int ml = e >> 5, dd = e & 31;
            long base = ((long)b_ * NTOK + t * 128 + ml) * (3 * CC);
            k_sh[e] = g_qkv[base + CC + hh * DH + dd];
            v_sh[e] = g_qkv[base + 2 * CC + hh * DH + dd];
        }
        __syncthreads();
        for (int ml = 0; ml < 128; ml++) {
            int m = t * 128 + ml;
            float dot = 0.0f;
            #pragma unroll
            for (int dd = 0; dd < 32; dd++) dot += q[dd] * k_sh[ml * 32 + dd];
            int jt = m >> 6, jh = (m >> 3) & 7, jw = m & 7;
            int idx = ((it - jt + 3) * 15 + (ih - jh + 7)) * 15 + (iw - jw + 7);
            float logit = dot + tbl_sh[idx] + ((reg_sh[m] == myreg) ? 0.0f : -100.0f);
            float e2 = expf(logit - maxv);
            denom += e2;
            #pragma unroll
            for (int dd = 0; dd < 32; dd++) out[dd] += e2 * v_sh[ml * 32 + dd];
        }
    }
    float rd = 1.0f / denom;
    float* orow = &g_xw[((long)b_ * NTOK + n) * CC + hh * DH];
    #pragma unroll
    for (int dd = 0; dd < 32; dd++) orow[dd] = out[dd] * rd;
}

// ---------------- LN(proj) + residual, scatter back to global layout ----------------
__global__ void attn_post_kernel(const float* __restrict__ x,
                                 const float* __restrict__ g, const float* __restrict__ b) {
    int r = blockIdx.x;
    int c = threadIdx.x;
    bool act = c < CC;
    float v = act ? g_pr[(long)r * CC + c] : 0.0f;
    __shared__ float s1[256], s2[256];
    s1[c] = v; s2[c] = v * v;
    __syncthreads();
    for (int s = 128; s > 0; s >>= 1) {
        if (c < s) { s1[c] += s1[c + s]; s2[c] += s2[c + s]; }
        __syncthreads();
    }
    float mean = s1[0] * (1.0f / CC);
    float var = s2[0] * (1.0f / CC) - mean * mean;
    if (act) {
        float ln = (v - mean) * rsqrtf(var + 1e-5f) * g[c] + b[c];
        int b_ = r >> 8, n = r & 255;
        int bb = b_ >> 7, w_ = b_ & 127;
        int wt = w_ >> 6, wh = (w_ >> 3) & 7, ww = w_ & 7;
        int it = n >> 6, ih = (n >> 3) & 7, iw = n & 7;
        int t = (wt * 4 + it + 2) & 7;
        int h = (wh * 8 + ih + 4) & 63;
        int w = (ww * 8 + iw + 4) & 63;
        long dst = ((long)((bb * TT + t) * HDIM + h) * WDIM + w) * CC + c;
        g_x1[dst] = x[dst] + ln;
    }
}

// ---------------- final LN(fc2) + residual -> output ----------------
__global__ void final_kernel(float* __restrict__ out,
                             const float* __restrict__ g, const float* __restrict__ b) {
    int r = blockIdx.x;
    int c = threadIdx.x;
    bool act = c < CC;
    float v = act ? g_pr[(long)r * CC + c] : 0.0f;
    __shared__ float s1[256], s2[256];
    s1[c] = v; s2[c] = v * v;
    __syncthreads();
    for (int s = 128; s > 0; s >>= 1) {
        if (c < s) { s1[c] += s1[c + s]; s2[c] += s2[c + s]; }
        __syncthreads();
    }
    float mean = s1[0] * (1.0f / CC);
    float var = s2[0] * (1.0f / CC) - mean * mean;
    if (act) {
        float ln = (v - mean) * rsqrtf(var + 1e-5f) * g[c] + b[c];
        out[(long)r * CC + c] = g_x1[(long)r * CC + c] + ln;
    }
}

// ---------------- launch ----------------
extern "C" void kernel_launch(void* const* d_in, const int* in_sizes, int n_in,
                              void* d_out, int out_size) {
    const float* x      = (const float*)d_in[0];
    const float* qkv_w  = (const float*)d_in[1];
    const float* qkv_b  = (const float*)d_in[2];
    const float* proj_w = (const float*)d_in[3];
    const float* proj_b = (const float*)d_in[4];
    const float* cpb_w1 = (const float*)d_in[5];
    const float* cpb_b1 = (const float*)d_in[6];
    const float* cpb_w2 = (const float*)d_in[7];
    const float* ls     = (const float*)d_in[8];
    const float* n1g    = (const float*)d_in[9];
    const float* n1b    = (const float*)d_in[10];
    const float* n2g    = (const float*)d_in[11];
    const float* n2b    = (const float*)d_in[12];
    const float* fc1_w  = (const float*)d_in[13];
    const float* fc1_b  = (const float*)d_in[14];
    const float* fc2_w  = (const float*)d_in[15];
    const float* fc2_b  = (const float*)d_in[16];
    float* out = (float*)d_out;

    cpb_kernel<<<CPB_M, CPB_H>>>(cpb_w1, cpb_b1, cpb_w2, ls);
    gather_kernel<<<(MROWS * CC) / 256, 256>>>(x);
    gemm_qkv_k<<<dim3((3 * CC) / 64, MROWS / 128), 256>>>(qkv_w, qkv_b);
    prenorm_kernel<<<(MROWS * HEADS * 2) / 8, 256>>>();
    attn_kernel<<<BWIN * HEADS, 256>>>();
    gemm_proj_k<<<dim3(CC / 64, MROWS / 128), 256>>>(proj_w, proj_b);
    attn_post_kernel<<<MROWS, 256>>>(x, n1g, n1b);
    gemm_fc1_k<<<dim3(HID / 64, MROWS / 128), 256>>>(fc1_w, fc1_b);
    gemm_fc2_k<<<dim3(CC / 64, MROWS / 128), 256>>>(fc2_w, fc2_b);
    final_kernel<<<MROWS, 256>>>(out, n2g, n2b);
}

// round 4
// speedup vs baseline: 2.1869x; 1.3677x over previous
#include <cuda_runtime.h>
#include <stdint.h>
#include <math.h>

// ---------------- problem constants ----------------
#define BQ     2
#define TT     8
#define HDIM   64
#define WDIM   64
#define CC     192
#define HEADS  6
#define DH     32
#define NTOK   256
#define NWIN   128
#define BWIN   256
#define MROWS  65536
#define HID    768
#define CPB_M  1575
#define CPB_H  512

typedef unsigned long long ull;

// ---------------- scratch ----------------
__device__ float g_xw [MROWS * CC];
__device__ float g_qkv[MROWS * 3 * CC];
__device__ float g_pr [MROWS * CC];
__device__ float g_x1 [MROWS * CC];
__device__ float g_h1 [MROWS * HID];
__device__ float g_tbl[CPB_M * HEADS];
__device__ float g_scale[HEADS];

// f32x2 packed helpers
#define FMA2(d, a, b) asm("fma.rn.f32x2 %0, %1, %2, %0;" : "+l"(d) : "l"(a), "l"(b))
#define MUL2(d, a, b) asm("mul.rn.f32x2 %0, %1, %2;" : "=l"(d) : "l"(a), "l"(b))
__device__ __forceinline__ ull pack2(float x) {
    ull r;
    asm("mov.b64 %0, {%1,%1};" : "=l"(r) : "r"(__float_as_uint(x)));
    return r;
}

// ---------------- CPB table ----------------
__global__ void cpb_kernel(const float* __restrict__ w1, const float* __restrict__ b1,
                           const float* __restrict__ w2, const float* __restrict__ ls) {
    int m = blockIdx.x;
    int tid = threadIdx.x;
    if (m == 0 && tid < HEADS)
        g_scale[tid] = expf(fminf(ls[tid], logf(100.0f)));

    int i = m / 225, rem = m % 225, j = rem / 15, k = rem % 15;
    float v0 = (float)(i - 3) * (8.0f / 3.0f);
    float v1 = (float)(j - 7) * (8.0f / 7.0f);
    float v2 = (float)(k - 7) * (8.0f / 7.0f);
    const float inv_l8 = 1.0f / log2f(8.0f);
    float c0 = copysignf(log2f(fabsf(v0) + 1.0f) * inv_l8, v0);
    float c1 = copysignf(log2f(fabsf(v1) + 1.0f) * inv_l8, v1);
    float c2 = copysignf(log2f(fabsf(v2) + 1.0f) * inv_l8, v2);

    float h = c0 * w1[tid * 3 + 0] + c1 * w1[tid * 3 + 1] + c2 * w1[tid * 3 + 2] + b1[tid];
    h = fmaxf(h, 0.0f);

    __shared__ float red[CPB_H];
    for (int hh = 0; hh < HEADS; hh++) {
        red[tid] = h * w2[hh * CPB_H + tid];
        __syncthreads();
        for (int s = CPB_H / 2; s > 0; s >>= 1) {
            if (tid < s) red[tid] += red[tid + s];
            __syncthreads();
        }
        if (tid == 0) {
            float t = red[0];
            g_tbl[m * HEADS + hh] = 16.0f / (1.0f + expf(-t));
        }
        __syncthreads();
    }
}

// ---------------- shift + window partition (gather, float4) ----------------
__global__ void gather_kernel(const float* __restrict__ x) {
    int idx = blockIdx.x * 256 + threadIdx.x;           // over MROWS*48
    int r = idx / 48, c4 = idx % 48;
    int b_ = r >> 8, n = r & 255;
    int bb = b_ >> 7, w_ = b_ & 127;
    int wt = w_ >> 6, wh = (w_ >> 3) & 7, ww = w_ & 7;
    int it = n >> 6, ih = (n >> 3) & 7, iw = n & 7;
    int t = (wt * 4 + it + 2) & 7;
    int h = (wh * 8 + ih + 4) & 63;
    int w = (ww * 8 + iw + 4) & 63;
    int src = ((bb * TT + t) * HDIM + h) * WDIM + w;
    *(float4*)&g_xw[(long)r * CC + c4 * 4] = *(const float4*)&x[(long)src * CC + c4 * 4];
}

// ---------------- tf32 tensor-core GEMM with register prefetch ----------------
__device__ __forceinline__ uint32_t f2tf32(float f) {
    uint32_t u;
    asm("cvt.rna.tf32.f32 %0, %1;" : "=r"(u) : "f"(f));
    return u;
}

template <int ACT>
__device__ __forceinline__ void gemm_tc_body(const float* __restrict__ A, const float* __restrict__ Wt,
                                             const float* __restrict__ bias, float* __restrict__ Cm,
                                             int M, int Nn, int K) {
    __shared__ uint32_t As[128][20];
    __shared__ uint32_t Bs[64][20];

    int tid = threadIdx.x;
    int lane = tid & 31;
    int warp = tid >> 5;
    int wm = warp >> 1;
    int wn = warp & 1;
    int m0 = blockIdx.y * 128;
    int n0 = blockIdx.x * 64;

    int grp = lane >> 2;
    int kc  = lane & 3;

    // per-thread load coords (fixed)
    int ra0 = tid >> 2,            ka0 = (tid & 3) * 4;
    int ra1 = (tid + 256) >> 2,    ka1 = ka0;
    int rb  = tid >> 2,            kb4 = (tid & 3) * 4;

    float acc[2][4][4];
    #pragma unroll
    for (int i = 0; i < 2; i++)
        #pragma unroll
        for (int j = 0; j < 4; j++)
            #pragma unroll
            for (int q = 0; q < 4; q++) acc[i][j][q] = 0.0f;

    float4 pa0 = *(const float4*)&A[(long)(m0 + ra0) * K + ka0];
    float4 pa1 = *(const float4*)&A[(long)(m0 + ra1) * K + ka1];
    float4 pb  = *(const float4*)&Wt[(long)(n0 + rb) * K + kb4];

    for (int k0 = 0; k0 < K; k0 += 16) {
        As[ra0][ka0 + 0] = f2tf32(pa0.x);
        As[ra0][ka0 + 1] = f2tf32(pa0.y);
        As[ra0][ka0 + 2] = f2tf32(pa0.z);
        As[ra0][ka0 + 3] = f2tf32(pa0.w);
        As[ra1][ka1 + 0] = f2tf32(pa1.x);
        As[ra1][ka1 + 1] = f2tf32(pa1.y);
        As[ra1][ka1 + 2] = f2tf32(pa1.z);
        As[ra1][ka1 + 3] = f2tf32(pa1.w);
        Bs[rb][kb4 + 0] = f2tf32(pb.x);
        Bs[rb][kb4 + 1] = f2tf32(pb.y);
        Bs[rb][kb4 + 2] = f2tf32(pb.z);
        Bs[rb][kb4 + 3] = f2tf32(pb.w);
        __syncthreads();

        int kn = k0 + 16;
        if (kn < K) {
            pa0 = *(const float4*)&A[(long)(m0 + ra0) * K + kn + ka0];
            pa1 = *(const float4*)&A[(long)(m0 + ra1) * K + kn + ka1];
            pb  = *(const float4*)&Wt[(long)(n0 + rb) * K + kn + kb4];
        }

        #pragma unroll
        for (int ks = 0; ks < 2; ks++) {
            int kb = ks * 8 + kc;
            uint32_t af[2][4];
            #pragma unroll
            for (int mt = 0; mt < 2; mt++) {
                int r = wm * 32 + mt * 16 + grp;
                af[mt][0] = As[r][kb];
                af[mt][1] = As[r + 8][kb];
                af[mt][2] = As[r][kb + 4];
                af[mt][3] = As[r + 8][kb + 4];
            }
            uint32_t bf[4][2];
            #pragma unroll
            for (int nt = 0; nt < 4; nt++) {
                int c = wn * 32 + nt * 8 + grp;
                bf[nt][0] = Bs[c][kb];
                bf[nt][1] = Bs[c][kb + 4];
            }
            #pragma unroll
            for (int mt = 0; mt < 2; mt++)
                #pragma unroll
                for (int nt = 0; nt < 4; nt++) {
                    asm volatile(
                        "mma.sync.aligned.m16n8k8.row.col.f32.tf32.tf32.f32 "
                        "{%0,%1,%2,%3}, {%4,%5,%6,%7}, {%8,%9}, {%0,%1,%2,%3};\n"
                        : "+f"(acc[mt][nt][0]), "+f"(acc[mt][nt][1]),
                          "+f"(acc[mt][nt][2]), "+f"(acc[mt][nt][3])
                        : "r"(af[mt][0]), "r"(af[mt][1]), "r"(af[mt][2]), "r"(af[mt][3]),
                          "r"(bf[nt][0]), "r"(bf[nt][1]));
                }
        }
        __syncthreads();
    }

    #pragma unroll
    for (int mt = 0; mt < 2; mt++) {
        int row = m0 + wm * 32 + mt * 16 + grp;
        #pragma unroll
        for (int nt = 0; nt < 4; nt++) {
            int col = n0 + wn * 32 + nt * 8 + kc * 2;
            float b0 = bias[col], b1 = bias[col + 1];
            float c0 = acc[mt][nt][0] + b0;
            float c1 = acc[mt][nt][1] + b1;
            float c2 = acc[mt][nt][2] + b0;
            float c3 = acc[mt][nt][3] + b1;
            if (ACT == 1) {
                c0 = 0.5f * c0 * (1.0f + erff(c0 * 0.70710678118654752f));
                c1 = 0.5f * c1 * (1.0f + erff(c1 * 0.70710678118654752f));
                c2 = 0.5f * c2 * (1.0f + erff(c2 * 0.70710678118654752f));
                c3 = 0.5f * c3 * (1.0f + erff(c3 * 0.70710678118654752f));
            }
            *(float2*)&Cm[(long)row * Nn + col] = make_float2(c0, c1);
            *(float2*)&Cm[(long)(row + 8) * Nn + col] = make_float2(c2, c3);
        }
    }
}

__global__ void __launch_bounds__(256) gemm_qkv_k (const float* Wt, const float* b) { gemm_tc_body<0>(g_xw, Wt, b, g_qkv, MROWS, 3 * CC, CC); }
__global__ void __launch_bounds__(256) gemm_proj_k(const float* Wt, const float* b) { gemm_tc_body<0>(g_xw, Wt, b, g_pr,  MROWS, CC,     CC); }
__global__ void __launch_bounds__(256) gemm_fc1_k (const float* Wt, const float* b) { gemm_tc_body<1>(g_x1, Wt, b, g_h1,  MROWS, HID,    CC); }
__global__ void __launch_bounds__(256) gemm_fc2_k (const float* Wt, const float* b) { gemm_tc_body<0>(g_h1, Wt, b, g_pr,  MROWS, CC,    HID); }

// ---------------- pre-normalize q,k rows (float4, 8-lane groups) ----------------
__global__ void prenorm_kernel() {
    int gtid = blockIdx.x * 256 + threadIdx.x;
    int vec = gtid >> 3;                   // over MROWS*HEADS*2
    int sub = threadIdx.x & 7;
    int which = vec & 1;
    int tmp = vec >> 1;
    int hh = tmp % HEADS;
    int row = tmp / HEADS;
    float4* p = (float4*)&g_qkv[(long)row * (3 * CC) + which * CC + hh * DH + sub * 4];
    float4 v = *p;
    float ss = v.x * v.x + v.y * v.y + v.z * v.z + v.w * v.w;
    ss += __shfl_xor_sync(0xffffffffu, ss, 4);
    ss += __shfl_xor_sync(0xffffffffu, ss, 2);
    ss += __shfl_xor_sync(0xffffffffu, ss, 1);
    float rn = 1.0f / fmaxf(sqrtf(ss), 1e-12f);
    if (which == 0) rn *= g_scale[hh];
    v.x *= rn; v.y *= rn; v.z *= rn; v.w *= rn;
    *p = v;
}

// ---------------- windowed attention: single pass, fixed max, f32x2 ----------------
__global__ void __launch_bounds__(256) attn_kernel() {
    int b_ = blockIdx.x / HEADS;
    int hh = blockIdx.x % HEADS;
    int n = threadIdx.x;

    __shared__ __align__(16) double k_sh[128 * 16];   // 128 keys x 16 f32x2 pairs
    __shared__ __align__(16) double v_sh[128 * 16];
    __shared__ float tbl_sh[CPB_M];
    __shared__ int   reg_sh[NTOK];
    __shared__ int   jidx_sh[NTOK];

    for (int i = n; i < CPB_M; i += 256) tbl_sh[i] = g_tbl[i * HEADS + hh];
    {
        int w_ = b_ & 127;
        int wt = w_ >> 6, wh = (w_ >> 3) & 7, ww = w_ & 7;
        int it = n >> 6, ih = (n >> 3) & 7, iw = n & 7;
        int ts = wt * 4 + it, hs = wh * 8 + ih, ws = ww * 8 + iw;
        int dt = (ts < 4) ? 0 : (ts < 6 ? 1 : 2);
        int dh = (hs < 56) ? 0 : (hs < 60 ? 1 : 2);
        int dw = (ws < 56) ? 0 : (ws < 60 ? 1 : 2);
        reg_sh[n] = dt * 9 + dh * 3 + dw;
        jidx_sh[n] = it * 225 + ih * 15 + iw;
    }
    __syncthreads();

    // q into packed pairs
    ull q2[16];
    {
        const double2* qp = (const double2*)&g_qkv[((long)b_ * NTOK + n) * (3 * CC) + hh * DH];
        #pragma unroll
        for (int f = 0; f < 8; f++) {
            double2 d = qp[f];
            q2[2 * f]     = __double_as_longlong(d.x);
            q2[2 * f + 1] = __double_as_longlong(d.y);
        }
    }
    int it = n >> 6, ih = (n >> 3) & 7, iw = n & 7;
    int myC = (it + 3) * 225 + (ih + 7) * 15 + (iw + 7);
    int myreg = reg_sh[n];
    float M = g_scale[hh] + 16.0f;    // logit upper bound: scale*cos + 16*sigmoid <= scale+16

    float denom = 0.0f;
    ull out2[16];
    #pragma unroll
    for (int f = 0; f < 16; f++) out2[f] = 0ull;

    for (int t = 0; t < 2; t++) {
        __syncthreads();
        #pragma unroll
        for (int i = 0; i < 4; i++) {
            int e = i * 256 + n;        // 0..1023 double2 slots
            int key = e >> 3, f2 = e & 7;
            long base = ((long)b_ * NTOK + t * 128 + key) * (3 * CC) + hh * DH + f2 * 4;
            ((double2*)&k_sh[key * 16])[f2] = *(const double2*)&g_qkv[base + CC];
            ((double2*)&v_sh[key * 16])[f2] = *(const double2*)&g_qkv[base + 2 * CC];
        }
        __syncthreads();
        for (int ml = 0; ml < 128; ml++) {
            int m = t * 128 + ml;
            const double2* kp = (const double2*)&k_sh[ml * 16];
            ull acc = 0ull;
            #pragma unroll
            for (int f = 0; f < 8; f++) {
                double2 kd = kp[f];
                FMA2(acc, q2[2 * f],     __double_as_longlong(kd.x));
                FMA2(acc, q2[2 * f + 1], __double_as_longlong(kd.y));
            }
            float dot = __uint_as_float((unsigned)acc) + __uint_as_float((unsigned)(acc >> 32));
            float logit = dot + tbl_sh[myC - jidx_sh[m]]
                        + ((reg_sh[m] == myreg) ? 0.0f : -100.0f) - M;
            float w = __expf(logit);
            denom += w;
            ull w2 = pack2(w);
            const double2* vp = (const double2*)&v_sh[ml * 16];
            #pragma unroll
            for (int f = 0; f < 8; f++) {
                double2 vd = vp[f];
                FMA2(out2[2 * f],     w2, __double_as_longlong(vd.x));
                FMA2(out2[2 * f + 1], w2, __double_as_longlong(vd.y));
            }
        }
    }
    ull rd2 = pack2(1.0f / denom);
    double* orow = (double*)&g_xw[((long)b_ * NTOK + n) * CC + hh * DH];
    #pragma unroll
    for (int f = 0; f < 16; f++) {
        ull r;
        MUL2(r, out2[f], rd2);
        orow[f] = __longlong_as_double(r);
    }
}

// ---------------- LN(proj) + residual scatter (192 threads, warp reduce) ----------------
__global__ void attn_post_kernel(const float* __restrict__ x,
                                 const float* __restrict__ g, const float* __restrict__ b) {
    int r = blockIdx.x;
    int c = threadIdx.x;     // 0..191
    float v = g_pr[(long)r * CC + c];
    float s1 = v, s2 = v * v;
    #pragma unroll
    for (int o = 16; o; o >>= 1) {
        s1 += __shfl_xor_sync(0xffffffffu, s1, o);
        s2 += __shfl_xor_sync(0xffffffffu, s2, o);
    }
    __shared__ float p1[6], p2[6];
    int w = c >> 5;
    if ((c & 31) == 0) { p1[w] = s1; p2[w] = s2; }
    __syncthreads();
    s1 = p1[0] + p1[1] + p1[2] + p1[3] + p1[4] + p1[5];
    s2 = p2[0] + p2[1] + p2[2] + p2[3] + p2[4] + p2[5];
    float mean = s1 * (1.0f / CC);
    float var = s2 * (1.0f / CC) - mean * mean;
    float ln = (v - mean) * rsqrtf(var + 1e-5f) * g[c] + b[c];
    int b_ = r >> 8, n = r & 255;
    int bb = b_ >> 7, w_ = b_ & 127;
    int wt = w_ >> 6, wh = (w_ >> 3) & 7, ww = w_ & 7;
    int it = n >> 6, ih = (n >> 3) & 7, iw = n & 7;
    int t = (wt * 4 + it + 2) & 7;
    int h = (wh * 8 + ih + 4) & 63;
    int ww2 = (ww * 8 + iw + 4) & 63;
    long dst = ((long)((bb * TT + t) * HDIM + h) * WDIM + ww2) * CC + c;
    g_x1[dst] = x[dst] + ln;
}

// ---------------- final LN(fc2) + residual -> output ----------------
__global__ void final_kernel(float* __restrict__ out,
                             const float* __restrict__ g, const float* __restrict__ b) {
    int r = blockIdx.x;
    int c = threadIdx.x;
    float v = g_pr[(long)r * CC + c];
    float s1 = v, s2 = v * v;
    #pragma unroll
    for (int o = 16; o; o >>= 1) {
        s1 += __shfl_xor_sync(0xffffffffu, s1, o);
        s2 += __shfl_xor_sync(0xffffffffu, s2, o);
    }
    __shared__ float p1[6], p2[6];
    int w = c >> 5;
    if ((c & 31) == 0) { p1[w] = s1; p2[w] = s2; }
    __syncthreads();
    s1 = p1[0] + p1[1] + p1[2] + p1[3] + p1[4] + p1[5];
    s2 = p2[0] + p2[1] + p2[2] + p2[3] + p2[4] + p2[5];
    float mean = s1 * (1.0f / CC);
    float var = s2 * (1.0f / CC) - mean * mean;
    float ln = (v - mean) * rsqrtf(var + 1e-5f) * g[c] + b[c];
    out[(long)r * CC + c] = g_x1[(long)r * CC + c] + ln;
}

// ---------------- launch ----------------
extern "C" void kernel_launch(void* const* d_in, const int* in_sizes, int n_in,
                              void* d_out, int out_size) {
    const float* x      = (const float*)d_in[0];
    const float* qkv_w  = (const float*)d_in[1];
    const float* qkv_b  = (const float*)d_in[2];
    const float* proj_w = (const float*)d_in[3];
    const float* proj_b = (const float*)d_in[4];
    const float* cpb_w1 = (const float*)d_in[5];
    const float* cpb_b1 = (const float*)d_in[6];
    const float* cpb_w2 = (const float*)d_in[7];
    const float* ls     = (const float*)d_in[8];
    const float* n1g    = (const float*)d_in[9];
    const float* n1b    = (const float*)d_in[10];
    const float* n2g    = (const float*)d_in[11];
    const float* n2b    = (const float*)d_in[12];
    const float* fc1_w  = (const float*)d_in[13];
    const float* fc1_b  = (const float*)d_in[14];
    const float* fc2_w  = (const float*)d_in[15];
    const float* fc2_b  = (const float*)d_in[16];
    float* out = (float*)d_out;

    cpb_kernel<<<CPB_M, CPB_H>>>(cpb_w1, cpb_b1, cpb_w2, ls);
    gather_kernel<<<(MROWS * 48) / 256, 256>>>(x);
    gemm_qkv_k<<<dim3((3 * CC) / 64, MROWS / 128), 256>>>(qkv_w, qkv_b);
    prenorm_kernel<<<(MROWS * HEADS * 2 * 8) / 256, 256>>>();
    attn_kernel<<<BWIN * HEADS, 256>>>();
    gemm_proj_k<<<dim3(CC / 64, MROWS / 128), 256>>>(proj_w, proj_b);
    attn_post_kernel<<<MROWS, 192>>>(x, n1g, n1b);
    gemm_fc1_k<<<dim3(HID / 64, MROWS / 128), 256>>>(fc1_w, fc1_b);
    gemm_fc2_k<<<dim3(CC / 64, MROWS / 128), 256>>>(fc2_w, fc2_b);
    final_kernel<<<MROWS, 192>>>(out, n2g, n2b);
}

// round 5
// speedup vs baseline: 2.2566x; 1.0319x over previous
#include <cuda_runtime.h>
#include <stdint.h>
#include <math.h>

// ---------------- problem constants ----------------
#define BQ     2
#define TT     8
#define HDIM   64
#define WDIM   64
#define CC     192
#define HEADS  6
#define DH     32
#define NTOK   256
#define NWIN   128
#define BWIN   256
#define MROWS  65536
#define HID    768
#define CPB_M  1575
#define CPB_H  512

typedef unsigned long long ull;

// ---------------- scratch ----------------
__device__ float g_xw [MROWS * CC];        // attention output (window layout)
__device__ float g_qkv[MROWS * 3 * CC];
__device__ float g_pr [MROWS * CC];
__device__ float g_x1 [MROWS * CC];
__device__ float g_h1 [MROWS * HID];
__device__ float g_tbl[CPB_M * HEADS];
__device__ float g_scale[HEADS];

// f32x2 packed helpers
#define FMA2(d, a, b) asm("fma.rn.f32x2 %0, %1, %2, %0;" : "+l"(d) : "l"(a), "l"(b))
#define MUL2(d, a, b) asm("mul.rn.f32x2 %0, %1, %2;" : "=l"(d) : "l"(a), "l"(b))
__device__ __forceinline__ ull pack2(float x) {
    ull r;
    asm("mov.b64 %0, {%1,%1};" : "=l"(r) : "r"(__float_as_uint(x)));
    return r;
}
__device__ __forceinline__ ull packxy(float x, float y) {
    ull r;
    asm("mov.b64 %0, {%1,%2};" : "=l"(r) : "r"(__float_as_uint(x)), "r"(__float_as_uint(y)));
    return r;
}

// window row -> source row in (B,T,H,W) layout (shift by +SHIFT = roll -SHIFT)
__device__ __forceinline__ long src_row(int r) {
    int b_ = r >> 8, n = r & 255;
    int bb = b_ >> 7, w_ = b_ & 127;
    int wt = w_ >> 6, wh = (w_ >> 3) & 7, ww = w_ & 7;
    int it = n >> 6, ih = (n >> 3) & 7, iw = n & 7;
    int t = (wt * 4 + it + 2) & 7;
    int h = (wh * 8 + ih + 4) & 63;
    int w = (ww * 8 + iw + 4) & 63;
    return (long)(((bb * TT + t) * HDIM + h) * WDIM + w);
}

// ---------------- CPB table ----------------
__global__ void cpb_kernel(const float* __restrict__ w1, const float* __restrict__ b1,
                           const float* __restrict__ w2, const float* __restrict__ ls) {
    int m = blockIdx.x;
    int tid = threadIdx.x;
    if (m == 0 && tid < HEADS)
        g_scale[tid] = expf(fminf(ls[tid], logf(100.0f)));

    int i = m / 225, rem = m % 225, j = rem / 15, k = rem % 15;
    float v0 = (float)(i - 3) * (8.0f / 3.0f);
    float v1 = (float)(j - 7) * (8.0f / 7.0f);
    float v2 = (float)(k - 7) * (8.0f / 7.0f);
    const float inv_l8 = 1.0f / log2f(8.0f);
    float c0 = copysignf(log2f(fabsf(v0) + 1.0f) * inv_l8, v0);
    float c1 = copysignf(log2f(fabsf(v1) + 1.0f) * inv_l8, v1);
    float c2 = copysignf(log2f(fabsf(v2) + 1.0f) * inv_l8, v2);

    float h = c0 * w1[tid * 3 + 0] + c1 * w1[tid * 3 + 1] + c2 * w1[tid * 3 + 2] + b1[tid];
    h = fmaxf(h, 0.0f);

    __shared__ float red[CPB_H];
    for (int hh = 0; hh < HEADS; hh++) {
        red[tid] = h * w2[hh * CPB_H + tid];
        __syncthreads();
        for (int s = CPB_H / 2; s > 0; s >>= 1) {
            if (tid < s) red[tid] += red[tid + s];
            __syncthreads();
        }
        if (tid == 0) {
            float t = red[0];
            g_tbl[m * HEADS + hh] = 16.0f / (1.0f + expf(-t));
        }
        __syncthreads();
    }
}

// ---------------- tf32 tensor-core GEMM, 2-stage smem, optional fused gather ----------------
__device__ __forceinline__ uint32_t f2tf32(float f) {
    uint32_t u;
    asm("cvt.rna.tf32.f32 %0, %1;" : "=r"(u) : "f"(f));
    return u;
}

template <int ACT, bool GATHER>
__device__ __forceinline__ void gemm_tc_body(const float* __restrict__ A, const float* __restrict__ Wt,
                                             const float* __restrict__ bias, float* __restrict__ Cm,
                                             int Nn, int K) {
    __shared__ uint32_t As[2][128][20];
    __shared__ uint32_t Bs[2][64][20];

    int tid = threadIdx.x;
    int lane = tid & 31;
    int warp = tid >> 5;
    int wm = warp >> 1;
    int wn = warp & 1;
    int m0 = blockIdx.y * 128;
    int n0 = blockIdx.x * 64;

    int grp = lane >> 2;
    int kc  = lane & 3;

    int ra0 = tid >> 2, ka = (tid & 3) * 4;
    int ra1 = ra0 + 64;
    int rb  = tid >> 2;

    long abase0, abase1;
    if (GATHER) {
        abase0 = src_row(m0 + ra0) * CC;
        abase1 = src_row(m0 + ra1) * CC;
    } else {
        abase0 = (long)(m0 + ra0) * K;
        abase1 = (long)(m0 + ra1) * K;
    }
    long bbase = (long)(n0 + rb) * K;

    float acc[2][4][4];
    #pragma unroll
    for (int i = 0; i < 2; i++)
        #pragma unroll
        for (int j = 0; j < 4; j++)
            #pragma unroll
            for (int q = 0; q < 4; q++) acc[i][j][q] = 0.0f;

    int nT = K / 16;
    float4 pa0 = *(const float4*)&A[abase0 + ka];
    float4 pa1 = *(const float4*)&A[abase1 + ka];
    float4 pb  = *(const float4*)&Wt[bbase + ka];

    // store stage 0
    {
        uint32_t (*as)[20] = As[0];
        uint32_t (*bs)[20] = Bs[0];
        as[ra0][ka + 0] = f2tf32(pa0.x); as[ra0][ka + 1] = f2tf32(pa0.y);
        as[ra0][ka + 2] = f2tf32(pa0.z); as[ra0][ka + 3] = f2tf32(pa0.w);
        as[ra1][ka + 0] = f2tf32(pa1.x); as[ra1][ka + 1] = f2tf32(pa1.y);
        as[ra1][ka + 2] = f2tf32(pa1.z); as[ra1][ka + 3] = f2tf32(pa1.w);
        bs[rb][ka + 0] = f2tf32(pb.x); bs[rb][ka + 1] = f2tf32(pb.y);
        bs[rb][ka + 2] = f2tf32(pb.z); bs[rb][ka + 3] = f2tf32(pb.w);
    }

    for (int k = 0; k < nT; k++) {
        if (k + 1 < nT) {
            int kn = (k + 1) * 16;
            pa0 = *(const float4*)&A[abase0 + kn + ka];
            pa1 = *(const float4*)&A[abase1 + kn + ka];
            pb  = *(const float4*)&Wt[bbase + kn + ka];
        }
        __syncthreads();
        uint32_t (*as)[20] = As[k & 1];
        uint32_t (*bs)[20] = Bs[k & 1];

        #pragma unroll
        for (int ks = 0; ks < 2; ks++) {
            int kb = ks * 8 + kc;
            uint32_t af[2][4];
            #pragma unroll
            for (int mt = 0; mt < 2; mt++) {
                int r = wm * 32 + mt * 16 + grp;
                af[mt][0] = as[r][kb];
                af[mt][1] = as[r + 8][kb];
                af[mt][2] = as[r][kb + 4];
                af[mt][3] = as[r + 8][kb + 4];
            }
            uint32_t bf[4][2];
            #pragma unroll
            for (int nt = 0; nt < 4; nt++) {
                int c = wn * 32 + nt * 8 + grp;
                bf[nt][0] = bs[c][kb];
                bf[nt][1] = bs[c][kb + 4];
            }
            #pragma unroll
            for (int mt = 0; mt < 2; mt++)
                #pragma unroll
                for (int nt = 0; nt < 4; nt++) {
                    asm volatile(
                        "mma.sync.aligned.m16n8k8.row.col.f32.tf32.tf32.f32 "
                        "{%0,%1,%2,%3}, {%4,%5,%6,%7}, {%8,%9}, {%0,%1,%2,%3};\n"
                        : "+f"(acc[mt][nt][0]), "+f"(acc[mt][nt][1]),
                          "+f"(acc[mt][nt][2]), "+f"(acc[mt][nt][3])
                        : "r"(af[mt][0]), "r"(af[mt][1]), "r"(af[mt][2]), "r"(af[mt][3]),
                          "r"(bf[nt][0]), "r"(bf[nt][1]));
                }
        }

        if (k + 1 < nT) {
            uint32_t (*asn)[20] = As[(k + 1) & 1];
            uint32_t (*bsn)[20] = Bs[(k + 1) & 1];
            asn[ra0][ka + 0] = f2tf32(pa0.x); asn[ra0][ka + 1] = f2tf32(pa0.y);
            asn[ra0][ka + 2] = f2tf32(pa0.z); asn[ra0][ka + 3] = f2tf32(pa0.w);
            asn[ra1][ka + 0] = f2tf32(pa1.x); asn[ra1][ka + 1] = f2tf32(pa1.y);
            asn[ra1][ka + 2] = f2tf32(pa1.z); asn[ra1][ka + 3] = f2tf32(pa1.w);
            bsn[rb][ka + 0] = f2tf32(pb.x); bsn[rb][ka + 1] = f2tf32(pb.y);
            bsn[rb][ka + 2] = f2tf32(pb.z); bsn[rb][ka + 3] = f2tf32(pb.w);
        }
    }

    #pragma unroll
    for (int mt = 0; mt < 2; mt++) {
        int row = m0 + wm * 32 + mt * 16 + grp;
        #pragma unroll
        for (int nt = 0; nt < 4; nt++) {
            int col = n0 + wn * 32 + nt * 8 + kc * 2;
            float b0 = bias[col], b1 = bias[col + 1];
            float c0 = acc[mt][nt][0] + b0;
            float c1 = acc[mt][nt][1] + b1;
            float c2 = acc[mt][nt][2] + b0;
            float c3 = acc[mt][nt][3] + b1;
            if (ACT == 1) {
                c0 = 0.5f * c0 * (1.0f + erff(c0 * 0.70710678118654752f));
                c1 = 0.5f * c1 * (1.0f + erff(c1 * 0.70710678118654752f));
                c2 = 0.5f * c2 * (1.0f + erff(c2 * 0.70710678118654752f));
                c3 = 0.5f * c3 * (1.0f + erff(c3 * 0.70710678118654752f));
            }
            *(float2*)&Cm[(long)row * Nn + col] = make_float2(c0, c1);
            *(float2*)&Cm[(long)(row + 8) * Nn + col] = make_float2(c2, c3);
        }
    }
}

__global__ void __launch_bounds__(256) gemm_qkv_k (const float* X, const float* Wt, const float* b) { gemm_tc_body<0, true >(X,    Wt, b, g_qkv, 3 * CC, CC); }
__global__ void __launch_bounds__(256) gemm_proj_k(const float* Wt, const float* b)                 { gemm_tc_body<0, false>(g_xw, Wt, b, g_pr,  CC,     CC); }
__global__ void __launch_bounds__(256) gemm_fc1_k (const float* Wt, const float* b)                 { gemm_tc_body<1, false>(g_x1, Wt, b, g_h1,  HID,    CC); }
__global__ void __launch_bounds__(256) gemm_fc2_k (const float* Wt, const float* b)                 { gemm_tc_body<0, false>(g_h1, Wt, b, g_pr,  CC,    HID); }

// ---------------- windowed attention: fused q/k normalize, single pass, f32x2 ----------------
__global__ void __launch_bounds__(256) attn_kernel() {
    int b_ = blockIdx.x / HEADS;
    int hh = blockIdx.x % HEADS;
    int n = threadIdx.x;

    __shared__ __align__(16) double k_sh[128 * 16];
    __shared__ __align__(16) double v_sh[128 * 16];
    __shared__ float tbl_sh[CPB_M];
    __shared__ int   reg_sh[NTOK];
    __shared__ int   jidx_sh[NTOK];

    for (int i = n; i < CPB_M; i += 256) tbl_sh[i] = g_tbl[i * HEADS + hh];
    {
        int w_ = b_ & 127;
        int wt = w_ >> 6, wh = (w_ >> 3) & 7, ww = w_ & 7;
        int it = n >> 6, ih = (n >> 3) & 7, iw = n & 7;
        int ts = wt * 4 + it, hs = wh * 8 + ih, ws = ww * 8 + iw;
        int dt = (ts < 4) ? 0 : (ts < 6 ? 1 : 2);
        int dh = (hs < 56) ? 0 : (hs < 60 ? 1 : 2);
        int dw = (ws < 56) ? 0 : (ws < 60 ? 1 : 2);
        reg_sh[n] = dt * 9 + dh * 3 + dw;
        jidx_sh[n] = it * 225 + ih * 15 + iw;
    }
    __syncthreads();

    // q: load raw, normalize, fold in logit scale, pack pairs
    float scale_h = g_scale[hh];
    ull q2[16];
    {
        const float4* qp = (const float4*)&g_qkv[((long)b_ * NTOK + n) * (3 * CC) + hh * DH];
        float4 qv[8];
        float ss = 0.0f;
        #pragma unroll
        for (int f = 0; f < 8; f++) {
            qv[f] = qp[f];
            ss += qv[f].x * qv[f].x + qv[f].y * qv[f].y + qv[f].z * qv[f].z + qv[f].w * qv[f].w;
        }
        float rn = scale_h / fmaxf(sqrtf(ss), 1e-12f);
        #pragma unroll
        for (int f = 0; f < 8; f++) {
            q2[2 * f]     = packxy(qv[f].x * rn, qv[f].y * rn);
            q2[2 * f + 1] = packxy(qv[f].z * rn, qv[f].w * rn);
        }
    }
    int it = n >> 6, ih = (n >> 3) & 7, iw = n & 7;
    int myC = (it + 3) * 225 + (ih + 7) * 15 + (iw + 7);
    int myreg = reg_sh[n];
    float M = scale_h + 16.0f;   // logit upper bound

    float denom = 0.0f;
    ull out2[16];
    #pragma unroll
    for (int f = 0; f < 16; f++) out2[f] = 0ull;

    for (int t = 0; t < 2; t++) {
        __syncthreads();
        #pragma unroll
        for (int i = 0; i < 4; i++) {
            int e = i * 256 + n;
            int key = e >> 3, f2 = e & 7;
            long base = ((long)b_ * NTOK + t * 128 + key) * (3 * CC) + hh * DH + f2 * 4;
            // k: normalize in flight (8 lanes cooperate per key)
            float4 kd = *(const float4*)&g_qkv[base + CC];
            float ss = kd.x * kd.x + kd.y * kd.y + kd.z * kd.z + kd.w * kd.w;
            ss += __shfl_xor_sync(0xffffffffu, ss, 1);
            ss += __shfl_xor_sync(0xffffffffu, ss, 2);
            ss += __shfl_xor_sync(0xffffffffu, ss, 4);
            float rn = 1.0f / fmaxf(sqrtf(ss), 1e-12f);
            double2 kp;
            kp.x = __longlong_as_double(packxy(kd.x * rn, kd.y * rn));
            kp.y = __longlong_as_double(packxy(kd.z * rn, kd.w * rn));
            ((double2*)&k_sh[key * 16])[f2] = kp;
            ((double2*)&v_sh[key * 16])[f2] = *(const double2*)&g_qkv[base + 2 * CC];
        }
        __syncthreads();
        for (int ml = 0; ml < 128; ml++) {
            int m = t * 128 + ml;
            const double2* kp = (const double2*)&k_sh[ml * 16];
            ull acc = 0ull;
            #pragma unroll
            for (int f = 0; f < 8; f++) {
                double2 kd = kp[f];
                FMA2(acc, q2[2 * f],     __double_as_longlong(kd.x));
                FMA2(acc, q2[2 * f + 1], __double_as_longlong(kd.y));
            }
            float dot = __uint_as_float((unsigned)acc) + __uint_as_float((unsigned)(acc >> 32));
            float logit = dot + tbl_sh[myC - jidx_sh[m]]
                        + ((reg_sh[m] == myreg) ? 0.0f : -100.0f) - M;
            float w = __expf(logit);
            denom += w;
            ull w2 = pack2(w);
            const double2* vp = (const double2*)&v_sh[ml * 16];
            #pragma unroll
            for (int f = 0; f < 8; f++) {
                double2 vd = vp[f];
                FMA2(out2[2 * f],     w2, __double_as_longlong(vd.x));
                FMA2(out2[2 * f + 1], w2, __double_as_longlong(vd.y));
            }
        }
    }
    ull rd2 = pack2(1.0f / denom);
    double* orow = (double*)&g_xw[((long)b_ * NTOK + n) * CC + hh * DH];
    #pragma unroll
    for (int f = 0; f < 16; f++) {
        ull r;
        MUL2(r, out2[f], rd2);
        orow[f] = __longlong_as_double(r);
    }
}

// ---------------- LN(proj) + residual scatter ----------------
__global__ void attn_post_kernel(const float* __restrict__ x,
                                 const float* __restrict__ g, const float* __restrict__ b) {
    int r = blockIdx.x;
    int c = threadIdx.x;
    float v = g_pr[(long)r * CC + c];
    float s1 = v, s2 = v * v;
    #pragma unroll
    for (int o = 16; o; o >>= 1) {
        s1 += __shfl_xor_sync(0xffffffffu, s1, o);
        s2 += __shfl_xor_sync(0xffffffffu, s2, o);
    }
    __shared__ float p1[6], p2[6];
    int w = c >> 5;
    if ((c & 31) == 0) { p1[w] = s1; p2[w] = s2; }
    __syncthreads();
    s1 = p1[0] + p1[1] + p1[2] + p1[3] + p1[4] + p1[5];
    s2 = p2[0] + p2[1] + p2[2] + p2[3] + p2[4] + p2[5];
    float mean = s1 * (1.0f / CC);
    float var = s2 * (1.0f / CC) - mean * mean;
    float ln = (v - mean) * rsqrtf(var + 1e-5f) * g[c] + b[c];
    long dst = src_row(r) * CC + c;
    g_x1[dst] = x[dst] + ln;
}

// ---------------- final LN(fc2) + residual -> output ----------------
__global__ void final_kernel(float* __restrict__ out,
                             const float* __restrict__ g, const float* __restrict__ b) {
    int r = blockIdx.x;
    int c = threadIdx.x;
    float v = g_pr[(long)r * CC + c];
    float s1 = v, s2 = v * v;
    #pragma unroll
    for (int o = 16; o; o >>= 1) {
        s1 += __shfl_xor_sync(0xffffffffu, s1, o);
        s2 += __shfl_xor_sync(0xffffffffu, s2, o);
    }
    __shared__ float p1[6], p2[6];
    int w = c >> 5;
    if ((c & 31) == 0) { p1[w] = s1; p2[w] = s2; }
    __syncthreads();
    s1 = p1[0] + p1[1] + p1[2] + p1[3] + p1[4] + p1[5];
    s2 = p2[0] + p2[1] + p2[2] + p2[3] + p2[4] + p2[5];
    float mean = s1 * (1.0f / CC);
    float var = s2 * (1.0f / CC) - mean * mean;
    float ln = (v - mean) * rsqrtf(var + 1e-5f) * g[c] + b[c];
    out[(long)r * CC + c] = g_x1[(long)r * CC + c] + ln;
}

// ---------------- launch ----------------
extern "C" void kernel_launch(void* const* d_in, const int* in_sizes, int n_in,
                              void* d_out, int out_size) {
    const float* x      = (const float*)d_in[0];
    const float* qkv_w  = (const float*)d_in[1];
    const float* qkv_b  = (const float*)d_in[2];
    const float* proj_w = (const float*)d_in[3];
    const float* proj_b = (const float*)d_in[4];
    const float* cpb_w1 = (const float*)d_in[5];
    const float* cpb_b1 = (const float*)d_in[6];
    const float* cpb_w2 = (const float*)d_in[7];
    const float* ls     = (const float*)d_in[8];
    const float* n1g    = (const float*)d_in[9];
    const float* n1b    = (const float*)d_in[10];
    const float* n2g    = (const float*)d_in[11];
    const float* n2b    = (const float*)d_in[12];
    const float* fc1_w  = (const float*)d_in[13];
    const float* fc1_b  = (const float*)d_in[14];
    const float* fc2_w  = (const float*)d_in[15];
    const float* fc2_b  = (const float*)d_in[16];
    float* out = (float*)d_out;

    cpb_kernel<<<CPB_M, CPB_H>>>(cpb_w1, cpb_b1, cpb_w2, ls);
    gemm_qkv_k<<<dim3((3 * CC) / 64, MROWS / 128), 256>>>(x, qkv_w, qkv_b);
    attn_kernel<<<BWIN * HEADS, 256>>>();
    gemm_proj_k<<<dim3(CC / 64, MROWS / 128), 256>>>(proj_w, proj_b);
    attn_post_kernel<<<MROWS, 192>>>(x, n1g, n1b);
    gemm_fc1_k<<<dim3(HID / 64, MROWS / 128), 256>>>(fc1_w, fc1_b);
    gemm_fc2_k<<<dim3(CC / 64, MROWS / 128), 256>>>(fc2_w, fc2_b);
    final_kernel<<<MROWS, 192>>>(out, n2g, n2b);
}